// round 3
// baseline (speedup 1.0000x reference)
#include <cuda_runtime.h>
#include <math.h>

#define DEPTH  8
#define DDIM   1024
#define DI     2048
#define NSTATE 16
#define DCONV  4
#define DTRANK 64
#define BB     2
#define LLEN   2048
#define ROWS   (BB*LLEN)          // 4096 token rows
#define XZW    (2*DI)             // 4096
#define XDBLW  (DTRANK + 2*NSTATE) // 96

// ---------------- scratch (static device globals; no allocation) ----------
__device__ float g_xz  [ROWS * XZW];    // in_proj output [4096,4096]; reused as out_proj output [4096,1024]
__device__ float g_xs  [ROWS * DI];     // conv+silu output
__device__ float g_xdbl[ROWS * XDBLW];  // x_proj output (dt | B | C)
__device__ float g_delta[ROWS * DI];    // softplus(dt @ Wdt + b)
__device__ float g_y   [ROWS * DI];     // scan output, gated in place
__device__ float g_x   [ROWS * DDIM];   // inter-layer activation

// ---------------- generic NT GEMM: C[M,N] = A[M,K] * W[N,K]^T -------------
// 64x64 tile, BK=16, 256 threads, 4x4 per thread. M must be /64; N guarded.
__global__ __launch_bounds__(256) void gemm_nt_kernel(
    const float* __restrict__ A, int lda,
    const float* __restrict__ W,               // [N,K] row-major (ldw = K)
    float* __restrict__ C, int ldc,
    int N, int K,
    int do_softplus, const float* __restrict__ bias)
{
    __shared__ float As[16][64];
    __shared__ float Ws[16][64];
    const int tid = threadIdx.x;
    const int tx = tid & 15, ty = tid >> 4;
    const int rowBase = blockIdx.y * 64;
    const int colBase = blockIdx.x * 64;
    const int lr = tid >> 2;         // 0..63
    const int lc = (tid & 3) << 2;   // 0,4,8,12

    float acc[4][4];
#pragma unroll
    for (int i = 0; i < 4; i++)
#pragma unroll
        for (int j = 0; j < 4; j++) acc[i][j] = 0.f;

    const float* Ap = A + (size_t)(rowBase + lr) * lda + lc;
    const int wrow = colBase + lr;
    const float* Wp = W + (size_t)wrow * K + lc;
    const bool wok = (wrow < N);

    for (int k0 = 0; k0 < K; k0 += 16) {
        float4 av = *(const float4*)(Ap + k0);
        float4 wv = wok ? *(const float4*)(Wp + k0) : make_float4(0.f, 0.f, 0.f, 0.f);
        As[lc + 0][lr] = av.x; As[lc + 1][lr] = av.y;
        As[lc + 2][lr] = av.z; As[lc + 3][lr] = av.w;
        Ws[lc + 0][lr] = wv.x; Ws[lc + 1][lr] = wv.y;
        Ws[lc + 2][lr] = wv.z; Ws[lc + 3][lr] = wv.w;
        __syncthreads();
#pragma unroll
        for (int k = 0; k < 16; k++) {
            float4 a = *(const float4*)&As[k][ty << 2];
            float4 b = *(const float4*)&Ws[k][tx << 2];
            acc[0][0] += a.x * b.x; acc[0][1] += a.x * b.y; acc[0][2] += a.x * b.z; acc[0][3] += a.x * b.w;
            acc[1][0] += a.y * b.x; acc[1][1] += a.y * b.y; acc[1][2] += a.y * b.z; acc[1][3] += a.y * b.w;
            acc[2][0] += a.z * b.x; acc[2][1] += a.z * b.y; acc[2][2] += a.z * b.z; acc[2][3] += a.z * b.w;
            acc[3][0] += a.w * b.x; acc[3][1] += a.w * b.y; acc[3][2] += a.w * b.z; acc[3][3] += a.w * b.w;
        }
        __syncthreads();
    }

#pragma unroll
    for (int i = 0; i < 4; i++) {
        const int r = rowBase + (ty << 2) + i;
#pragma unroll
        for (int j = 0; j < 4; j++) {
            const int c = colBase + (tx << 2) + j;
            if (c < N) {
                float v = acc[i][j];
                if (do_softplus) {
                    v += bias[c];
                    // softplus = max(v,0) + log1p(exp(-|v|))  (jax logaddexp(v,0))
                    v = fmaxf(v, 0.f) + log1pf(expf(-fabsf(v)));
                }
                C[(size_t)r * ldc + c] = v;
            }
        }
    }
}

// ---------------- depthwise causal conv (width 4) + bias + silu -----------
__global__ __launch_bounds__(256) void conv_silu_kernel(
    const float* __restrict__ xz,  // [ROWS, XZW], first DI cols = xs
    const float* __restrict__ cw,  // [DI,4]
    const float* __restrict__ cb,  // [DI]
    float* __restrict__ xs)        // [ROWS, DI]
{
    const int i = blockIdx.x * blockDim.x + threadIdx.x;
    if (i >= ROWS * DI) return;
    const int d = i & (DI - 1);
    const int r = i >> 11;          // DI = 2048
    const int t = r & (LLEN - 1);   // position within sequence
    float acc = cb[d];
    const float* base = xz + (size_t)r * XZW + d;
#pragma unroll
    for (int j = 0; j < DCONV; j++) {
        const int tt = t - (DCONV - 1) + j;
        if (tt >= 0)
            acc += cw[d * DCONV + j] * base[(long)(tt - t) * XZW];
    }
    xs[i] = acc / (1.f + __expf(-acc));   // silu
}

// ---------------- selective scan: 16 lanes per (b,d) channel --------------
__global__ __launch_bounds__(128) void scan_kernel(
    const float* __restrict__ xs,    // [ROWS, DI]
    const float* __restrict__ delta, // [ROWS, DI]
    const float* __restrict__ xdbl,  // [ROWS, 96]: [0:64)=dt, [64:80)=B, [80:96)=C
    const float* __restrict__ A_log, // [DI, 16]
    const float* __restrict__ Dp,    // [DI]
    float* __restrict__ y)           // [ROWS, DI]
{
    const int lane = threadIdx.x & 15;
    const int ch = blockIdx.x * (blockDim.x >> 4) + (threadIdx.x >> 4);
    const int b = ch / DI, d = ch & (DI - 1);
    const float A  = -expf(A_log[d * NSTATE + lane]);
    const float Dd = Dp[d];

    const float* xsP = xs    + (size_t)b * LLEN * DI + d;
    const float* dlP = delta + (size_t)b * LLEN * DI + d;
    const float* bcP = xdbl  + (size_t)b * LLEN * XDBLW + DTRANK + lane;
    float*       yP  = y     + (size_t)b * LLEN * DI + d;

    float h = 0.f;
    for (int t = 0; t < LLEN; t++) {
        const float dt = dlP[0];
        const float xt = xsP[0];
        const float Bt = bcP[0];
        const float Ct = bcP[NSTATE];
        const float dA = __expf(dt * A);       // dt>=0, A<0 -> bounded (0,1]
        h = dA * h + (dt * xt) * Bt;
        float p = h * Ct;
        p += __shfl_xor_sync(0xffffffffu, p, 1);
        p += __shfl_xor_sync(0xffffffffu, p, 2);
        p += __shfl_xor_sync(0xffffffffu, p, 4);
        p += __shfl_xor_sync(0xffffffffu, p, 8);
        if (lane == 0) yP[0] = p + Dd * xt;
        xsP += DI; dlP += DI; bcP += XDBLW; yP += DI;
    }
}

// ---------------- gate: y *= silu(z) --------------------------------------
__global__ __launch_bounds__(256) void gate_kernel(
    float* __restrict__ y, const float* __restrict__ xz)
{
    const int i = blockIdx.x * blockDim.x + threadIdx.x;
    if (i >= ROWS * DI) return;
    const int d = i & (DI - 1);
    const int r = i >> 11;
    const float z = xz[(size_t)r * XZW + DI + d];
    y[i] *= z / (1.f + __expf(-z));
}

// ---------------- rmsnorm per row (DIM=1024, 256 threads) -----------------
__global__ __launch_bounds__(256) void rmsnorm_kernel(
    const float* __restrict__ in, const float* __restrict__ w,
    float* __restrict__ out)
{
    const int r = blockIdx.x;
    const int tid = threadIdx.x;
    const float* row = in + (size_t)r * DDIM;
    float v[4];
    float ss = 0.f;
#pragma unroll
    for (int j = 0; j < 4; j++) {
        v[j] = row[tid + j * 256];
        ss += v[j] * v[j];
    }
#pragma unroll
    for (int o = 16; o > 0; o >>= 1) ss += __shfl_xor_sync(0xffffffffu, ss, o);
    __shared__ float ws[8];
    if ((tid & 31) == 0) ws[tid >> 5] = ss;
    __syncthreads();
    float tot = 0.f;
#pragma unroll
    for (int k = 0; k < 8; k++) tot += ws[k];
    const float inv = rsqrtf(tot * (1.f / (float)DDIM) + 1e-5f);
#pragma unroll
    for (int j = 0; j < 4; j++)
        out[(size_t)r * DDIM + tid + j * 256] = v[j] * inv * w[tid + j * 256];
}

// ---------------- host launch ---------------------------------------------
extern "C" void kernel_launch(void* const* d_in, const int* in_sizes, int n_in,
                              void* d_out, int out_size)
{
    const float* x0   = (const float*)d_in[0];
    const float* Wi   = (const float*)d_in[1];   // [8, 4096, 1024]
    const float* cw   = (const float*)d_in[2];   // [8, 2048, 4]
    const float* cb   = (const float*)d_in[3];   // [8, 2048]
    const float* Wx   = (const float*)d_in[4];   // [8, 96, 2048]
    const float* Wdt  = (const float*)d_in[5];   // [8, 2048, 64]
    const float* bdt  = (const float*)d_in[6];   // [8, 2048]
    const float* Alog = (const float*)d_in[7];   // [8, 2048, 16]
    const float* Dp   = (const float*)d_in[8];   // [8, 2048]
    const float* Wo   = (const float*)d_in[9];   // [8, 1024, 2048]
    const float* rw   = (const float*)d_in[10];  // [8, 1024]

    float *xz, *xs, *xdbl, *delta, *y, *xb;
    cudaGetSymbolAddress((void**)&xz,    g_xz);
    cudaGetSymbolAddress((void**)&xs,    g_xs);
    cudaGetSymbolAddress((void**)&xdbl,  g_xdbl);
    cudaGetSymbolAddress((void**)&delta, g_delta);
    cudaGetSymbolAddress((void**)&y,     g_y);
    cudaGetSymbolAddress((void**)&xb,    g_x);

    const float* xin = x0;
    for (int l = 0; l < DEPTH; l++) {
        // 1) in_proj: [4096,1024] x [4096,1024]^T -> xz [4096,4096]
        gemm_nt_kernel<<<dim3(XZW / 64, ROWS / 64), 256>>>(
            xin, DDIM, Wi + (size_t)l * XZW * DDIM, xz, XZW, XZW, DDIM, 0, nullptr);

        // 2) depthwise causal conv + silu -> xs [4096,2048]
        conv_silu_kernel<<<(ROWS * DI) / 256, 256>>>(
            xz, cw + (size_t)l * DI * DCONV, cb + (size_t)l * DI, xs);

        // 3) x_proj: [4096,2048] x [96,2048]^T -> xdbl [4096,96]
        gemm_nt_kernel<<<dim3((XDBLW + 63) / 64, ROWS / 64), 256>>>(
            xs, DI, Wx + (size_t)l * XDBLW * DI, xdbl, XDBLW, XDBLW, DI, 0, nullptr);

        // 4) dt_proj + bias + softplus: [4096,64(ld 96)] x [2048,64]^T -> delta
        gemm_nt_kernel<<<dim3(DI / 64, ROWS / 64), 256>>>(
            xdbl, XDBLW, Wdt + (size_t)l * DI * DTRANK, delta, DI, DI, DTRANK,
            1, bdt + (size_t)l * DI);

        // 5) selective scan (+ D skip) -> y [4096,2048]
        scan_kernel<<<(BB * DI) / 8, 128>>>(
            xs, delta, xdbl, Alog + (size_t)l * DI * NSTATE, Dp + (size_t)l * DI, y);

        // 6) gate: y *= silu(z)
        gate_kernel<<<(ROWS * DI) / 256, 256>>>(y, xz);

        // 7) out_proj: [4096,2048] x [1024,2048]^T -> xz (reused) [4096,1024]
        gemm_nt_kernel<<<dim3(DDIM / 64, ROWS / 64), 256>>>(
            y, DI, Wo + (size_t)l * DDIM * DI, xz, DDIM, DDIM, DI, 0, nullptr);

        // 8) rmsnorm -> next layer input (or final output)
        float* outp = (l == DEPTH - 1) ? (float*)d_out : xb;
        rmsnorm_kernel<<<ROWS, 256>>>(xz, rw + (size_t)l * DDIM, outp);
        xin = xb;
    }
}